// round 2
// baseline (speedup 1.0000x reference)
#include <cuda_runtime.h>
#include <math.h>

// Problem constants
#define B_  2
#define T_  2048
#define D_  2048
#define NH  16
#define HD  128
#define FF  64          // HD/2 rotary freqs
#define M_  (B_*T_)     // 4096 flattened rows

// ---------------------------------------------------------------------------
// Scratch (static device globals; no allocation allowed)
// ---------------------------------------------------------------------------
__device__ float g_qkv[(size_t)M_ * 3 * D_];   // [B*T, 3D]
__device__ float g_q  [(size_t)M_ * D_];       // [B,N,T,H] head-major
__device__ float g_k  [(size_t)M_ * D_];
__device__ float g_v  [(size_t)M_ * D_];
__device__ float g_ao [(size_t)M_ * D_];       // attention out, [B,T,N*H]

// ---------------------------------------------------------------------------
// SGEMM: C[M,N] = A[M,K] @ B[K,N], all row-major fp32.
// 128x128 block tile, BK=8, 8x8 per-thread, 256 threads.
// Requires M%128==0, N%128==0, K%8==0 (true for all uses here).
// ---------------------------------------------------------------------------
__global__ void __launch_bounds__(256) sgemm_kernel(
    const float* __restrict__ A, const float* __restrict__ Bm,
    float* __restrict__ C, int M, int N, int K)
{
    __shared__ float As[8][128];
    __shared__ float Bs[8][128];

    const int tid = threadIdx.x;
    const int bx = blockIdx.x, by = blockIdx.y;
    const int ty = tid >> 4, tx = tid & 15;   // 16x16 thread grid

    const int arow = tid >> 1;            // 0..127
    const int ac   = (tid & 1) * 4;       // 0 or 4
    const int brow = tid >> 5;            // 0..7
    const int bc4  = (tid & 31) * 4;      // 0..124

    float acc[8][8];
#pragma unroll
    for (int i = 0; i < 8; ++i)
#pragma unroll
        for (int j = 0; j < 8; ++j) acc[i][j] = 0.f;

    const size_t aBase = (size_t)(by * 128 + arow) * K + ac;
    const size_t bCol  = (size_t)bx * 128 + bc4;

    for (int k0 = 0; k0 < K; k0 += 8) {
        float4 av = *(const float4*)&A[aBase + k0];
        As[ac + 0][arow] = av.x;
        As[ac + 1][arow] = av.y;
        As[ac + 2][arow] = av.z;
        As[ac + 3][arow] = av.w;
        float4 bv = *(const float4*)&Bm[(size_t)(k0 + brow) * N + bCol];
        *(float4*)&Bs[brow][bc4] = bv;
        __syncthreads();

#pragma unroll
        for (int kk = 0; kk < 8; ++kk) {
            float ra[8], rb[8];
            *(float4*)&ra[0] = *(float4*)&As[kk][ty * 8];
            *(float4*)&ra[4] = *(float4*)&As[kk][ty * 8 + 4];
            *(float4*)&rb[0] = *(float4*)&Bs[kk][tx * 8];
            *(float4*)&rb[4] = *(float4*)&Bs[kk][tx * 8 + 4];
#pragma unroll
            for (int i = 0; i < 8; ++i)
#pragma unroll
                for (int j = 0; j < 8; ++j)
                    acc[i][j] += ra[i] * rb[j];
        }
        __syncthreads();
    }

#pragma unroll
    for (int i = 0; i < 8; ++i) {
        size_t row = (size_t)(by * 128 + ty * 8 + i);
        float* cp = &C[row * N + bx * 128 + tx * 8];
        *(float4*)&cp[0] = *(float4*)&acc[i][0];
        *(float4*)&cp[4] = *(float4*)&acc[i][4];
    }
}

// ---------------------------------------------------------------------------
// RoPE + split + transpose to head-major [B,N,T,H].
// Rope applied to K and V (NOT Q) per the reference module.
// One thread per (b,t,n,f) rotary pair.
// ---------------------------------------------------------------------------
__global__ void rope_split_kernel(
    const float* __restrict__ qkv,
    const float* __restrict__ cosT, const float* __restrict__ sinT,
    float* __restrict__ q, float* __restrict__ k, float* __restrict__ v)
{
    int idx = blockIdx.x * blockDim.x + threadIdx.x;
    if (idx >= B_ * T_ * NH * FF) return;
    int f = idx & (FF - 1);
    int n = (idx >> 6) & (NH - 1);
    int t = (idx >> 10) & (T_ - 1);
    int b = idx >> 21;

    size_t base = (size_t)(b * T_ + t) * (3 * D_);
    int col = n * HD + 2 * f;
    float c = cosT[t * FF + f];
    float s = sinT[t * FF + f];
    size_t ho = ((size_t)(b * NH + n) * T_ + t) * HD + 2 * f;

    float2 qp = *(const float2*)&qkv[base + col];
    float2 kp = *(const float2*)&qkv[base + D_ + col];
    float2 vp = *(const float2*)&qkv[base + 2 * D_ + col];

    float2 ko = make_float2(kp.x * c - kp.y * s, kp.x * s + kp.y * c);
    float2 vo = make_float2(vp.x * c - vp.y * s, vp.x * s + vp.y * c);

    *(float2*)&q[ho] = qp;
    *(float2*)&k[ho] = ko;
    *(float2*)&v[ho] = vo;
}

// ---------------------------------------------------------------------------
// Flash attention (fp32, causal). One block per (q-tile of 64, head, batch).
// 256 threads. Streaming softmax; O in registers (4 rows x 8 cols / thread).
// Writes O in [B,T,N*H] layout so the final projection is a plain GEMM.
// ---------------------------------------------------------------------------
#define QS_STRIDE 132
#define SS_STRIDE 65
#define ATT_SMEM_FLOATS (3 * 64 * QS_STRIDE + 64 * SS_STRIDE + 3 * 64)
#define ATT_SMEM_BYTES  (ATT_SMEM_FLOATS * 4)

__global__ void __launch_bounds__(256) attn_kernel(
    const float* __restrict__ Q, const float* __restrict__ K,
    const float* __restrict__ V, float* __restrict__ O)
{
    const int qt = blockIdx.x, n = blockIdx.y, b = blockIdx.z;
    const int q0 = qt * 64;
    const int tid = threadIdx.x;

    extern __shared__ float sm[];
    float* Qs  = sm;                          // 64 x 132
    float* Ks  = Qs + 64 * QS_STRIDE;         // 64 x 132
    float* Vs  = Ks + 64 * QS_STRIDE;         // 64 x 132
    float* Ss  = Vs + 64 * QS_STRIDE;         // 64 x 65
    float* m_s = Ss + 64 * SS_STRIDE;         // 64
    float* l_s = m_s + 64;                    // 64
    float* a_s = l_s + 64;                    // 64

    const size_t headBase = (size_t)(b * NH + n) * T_ * HD;

    // Load Q tile (64 x 128) once
#pragma unroll
    for (int t = 0; t < 8; ++t) {
        int idx = tid + t * 256;              // float4 index, 2048 total
        int r = idx >> 5, c4 = (idx & 31) * 4;
        *(float4*)&Qs[r * QS_STRIDE + c4] =
            *(const float4*)&Q[headBase + (size_t)(q0 + r) * HD + c4];
    }
    if (tid < 64) { m_s[tid] = -1e30f; l_s[tid] = 0.f; }

    float o[4][8];
#pragma unroll
    for (int i = 0; i < 4; ++i)
#pragma unroll
        for (int j = 0; j < 8; ++j) o[i][j] = 0.f;

    const int rg = tid >> 4;   // row group (0..15) -> rows rg*4 .. rg*4+3
    const int cg = tid & 15;   // col group
    const float scale = 0.08838834764831845f;  // 1/sqrt(128)

    const int nkt = qt + 1;    // causal: only tiles with k0 <= q0
    for (int kt = 0; kt < nkt; ++kt) {
        const int k0 = kt * 64;
        __syncthreads();       // previous O-update done before K/V overwrite

        // Load K and V tiles (each 64 x 128)
#pragma unroll
        for (int t = 0; t < 8; ++t) {
            int idx = tid + t * 256;
            int r = idx >> 5, c4 = (idx & 31) * 4;
            size_t g = headBase + (size_t)(k0 + r) * HD + c4;
            *(float4*)&Ks[r * QS_STRIDE + c4] = *(const float4*)&K[g];
            *(float4*)&Vs[r * QS_STRIDE + c4] = *(const float4*)&V[g];
        }
        __syncthreads();

        // S = scale * Q @ K^T  (each thread: 4x4 of 64x64 tile)
        float acc[4][4];
#pragma unroll
        for (int i = 0; i < 4; ++i)
#pragma unroll
            for (int j = 0; j < 4; ++j) acc[i][j] = 0.f;

#pragma unroll 4
        for (int h4 = 0; h4 < 32; ++h4) {
            float4 qv[4], kv[4];
#pragma unroll
            for (int i = 0; i < 4; ++i)
                qv[i] = *(float4*)&Qs[(rg * 4 + i) * QS_STRIDE + h4 * 4];
#pragma unroll
            for (int j = 0; j < 4; ++j)
                kv[j] = *(float4*)&Ks[(cg * 4 + j) * QS_STRIDE + h4 * 4];
#pragma unroll
            for (int i = 0; i < 4; ++i)
#pragma unroll
                for (int j = 0; j < 4; ++j)
                    acc[i][j] += qv[i].x * kv[j].x + qv[i].y * kv[j].y
                               + qv[i].z * kv[j].z + qv[i].w * kv[j].w;
        }

        // scale + causal mask + store to smem
#pragma unroll
        for (int i = 0; i < 4; ++i) {
            int qg = q0 + rg * 4 + i;
#pragma unroll
            for (int j = 0; j < 4; ++j) {
                int kg = k0 + cg * 4 + j;
                float vsl = acc[i][j] * scale;
                if (kg > qg) vsl = -1e30f;
                Ss[(rg * 4 + i) * SS_STRIDE + cg * 4 + j] = vsl;
            }
        }
        __syncthreads();

        // Streaming softmax stats (one thread per row)
        if (tid < 64) {
            float mold = m_s[tid], lold = l_s[tid];
            float* row = &Ss[tid * SS_STRIDE];
            float rmax = -1e30f;
#pragma unroll 8
            for (int c = 0; c < 64; ++c) rmax = fmaxf(rmax, row[c]);
            float mnew = fmaxf(mold, rmax);
            float alpha = __expf(mold - mnew);
            float ssum = 0.f;
#pragma unroll 8
            for (int c = 0; c < 64; ++c) {
                float p = __expf(row[c] - mnew);
                row[c] = p;
                ssum += p;
            }
            m_s[tid] = mnew;
            l_s[tid] = lold * alpha + ssum;
            a_s[tid] = alpha;
        }
        __syncthreads();

        // O = O*alpha + P @ V   (each thread: 4 rows x 8 cols of 64x128)
        float al[4];
#pragma unroll
        for (int i = 0; i < 4; ++i) al[i] = a_s[rg * 4 + i];
#pragma unroll
        for (int i = 0; i < 4; ++i)
#pragma unroll
            for (int j = 0; j < 8; ++j) o[i][j] *= al[i];

#pragma unroll 4
        for (int kk = 0; kk < 64; ++kk) {
            float p[4];
#pragma unroll
            for (int i = 0; i < 4; ++i) p[i] = Ss[(rg * 4 + i) * SS_STRIDE + kk];
            float4 v0 = *(float4*)&Vs[kk * QS_STRIDE + cg * 8];
            float4 v1 = *(float4*)&Vs[kk * QS_STRIDE + cg * 8 + 4];
#pragma unroll
            for (int i = 0; i < 4; ++i) {
                o[i][0] += p[i] * v0.x; o[i][1] += p[i] * v0.y;
                o[i][2] += p[i] * v0.z; o[i][3] += p[i] * v0.w;
                o[i][4] += p[i] * v1.x; o[i][5] += p[i] * v1.y;
                o[i][6] += p[i] * v1.z; o[i][7] += p[i] * v1.w;
            }
        }
    }

    // Normalize and write out: O[b, q, n*H + col]
#pragma unroll
    for (int i = 0; i < 4; ++i) {
        int qg = q0 + rg * 4 + i;
        float inv = 1.f / l_s[rg * 4 + i];
        float4 w0, w1;
        w0.x = o[i][0] * inv; w0.y = o[i][1] * inv;
        w0.z = o[i][2] * inv; w0.w = o[i][3] * inv;
        w1.x = o[i][4] * inv; w1.y = o[i][5] * inv;
        w1.z = o[i][6] * inv; w1.w = o[i][7] * inv;
        size_t ob = (size_t)(b * T_ + qg) * D_ + n * HD + cg * 8;
        *(float4*)&O[ob]     = w0;
        *(float4*)&O[ob + 4] = w1;
    }
}

// ---------------------------------------------------------------------------
// Launch
// ---------------------------------------------------------------------------
extern "C" void kernel_launch(void* const* d_in, const int* in_sizes, int n_in,
                              void* d_out, int out_size)
{
    const float* x      = (const float*)d_in[0];
    // d_in[1] = mask (causal, structurally known) -- unused
    const float* cosT   = (const float*)d_in[2];
    const float* sinT   = (const float*)d_in[3];
    const float* w_attn = (const float*)d_in[4];
    const float* w_out  = (const float*)d_in[5];
    float* out = (float*)d_out;

    float *qkv, *q, *k, *v, *ao;
    cudaGetSymbolAddress((void**)&qkv, g_qkv);
    cudaGetSymbolAddress((void**)&q,   g_q);
    cudaGetSymbolAddress((void**)&k,   g_k);
    cudaGetSymbolAddress((void**)&v,   g_v);
    cudaGetSymbolAddress((void**)&ao,  g_ao);

    // 1) QKV projection: [4096,2048] @ [2048,6144]
    sgemm_kernel<<<dim3(3 * D_ / 128, M_ / 128), 256>>>(x, w_attn, qkv, M_, 3 * D_, D_);

    // 2) RoPE (K,V) + split + transpose to head-major
    {
        int total = B_ * T_ * NH * FF;
        rope_split_kernel<<<(total + 255) / 256, 256>>>(qkv, cosT, sinT, q, k, v);
    }

    // 3) Causal flash attention
    cudaFuncSetAttribute(attn_kernel, cudaFuncAttributeMaxDynamicSharedMemorySize,
                         ATT_SMEM_BYTES);
    attn_kernel<<<dim3(T_ / 64, NH, B_), 256, ATT_SMEM_BYTES>>>(q, k, v, ao);

    // 4) Output projection: [4096,2048] @ [2048,2048]
    sgemm_kernel<<<dim3(D_ / 128, M_ / 128), 256>>>(ao, w_out, out, M_, D_, D_);
}

// round 4
// speedup vs baseline: 1.5155x; 1.5155x over previous
#include <cuda_runtime.h>
#include <math.h>
#include <stdint.h>

// Problem constants
#define B_  2
#define T_  2048
#define D_  2048
#define NH  16
#define HD  128
#define FF  64          // HD/2 rotary freqs
#define M_  (B_*T_)     // 4096 flattened rows

// ---------------------------------------------------------------------------
// Scratch (static device globals; no allocation allowed)
// ---------------------------------------------------------------------------
__device__ float g_qkv[(size_t)M_ * 3 * D_];   // [B*T, 3D]
__device__ float g_q  [(size_t)M_ * D_];       // [B,N,T,H] head-major
__device__ float g_k  [(size_t)M_ * D_];
__device__ float g_v  [(size_t)M_ * D_];
__device__ float g_ao [(size_t)M_ * D_];       // attention out, [B,T,N*H]

// ---------------------------------------------------------------------------
// tf32 helpers
// ---------------------------------------------------------------------------
__device__ __forceinline__ uint32_t to_tf32(float x) {
    uint32_t y;
    asm("cvt.rna.tf32.f32 %0, %1;" : "=r"(y) : "f"(x));
    return y;
}

__device__ __forceinline__ void mma_tf32(
    float* c, uint32_t a0, uint32_t a1, uint32_t a2, uint32_t a3,
    uint32_t b0, uint32_t b1)
{
    asm volatile(
        "mma.sync.aligned.m16n8k8.row.col.f32.tf32.tf32.f32 "
        "{%0,%1,%2,%3}, {%4,%5,%6,%7}, {%8,%9}, {%0,%1,%2,%3};"
        : "+f"(c[0]), "+f"(c[1]), "+f"(c[2]), "+f"(c[3])
        : "r"(a0), "r"(a1), "r"(a2), "r"(a3), "r"(b0), "r"(b1));
}

// ---------------------------------------------------------------------------
// TF32 tensor-core GEMM: C[M,N] = A[M,K] @ B[K,N], row-major fp32 in/out.
// 128x128x16 block tile, 256 threads (8 warps as 4x2), 32x64 warp tile.
// smem stride 136 (pad 8) => A and B fragment loads are bank-conflict-free.
// Requires M%128==0, N%128==0, K%16==0.
// ---------------------------------------------------------------------------
#define GS 136   // smem row stride in 32-bit words

__global__ void __launch_bounds__(256) tf32_gemm_kernel(
    const float* __restrict__ A, const float* __restrict__ Bm,
    float* __restrict__ C, int M, int N, int K)
{
    __shared__ uint32_t As[16 * GS];   // [k][m] (transposed), tf32 bits
    __shared__ uint32_t Bs[16 * GS];   // [k][n], tf32 bits

    const int tid  = threadIdx.x;
    const int bx = blockIdx.x, by = blockIdx.y;
    const int warp = tid >> 5, lane = tid & 31;
    const int wm = warp >> 1, wn = warp & 1;      // 4 x 2 warp grid
    const int gid = lane >> 2, tig = lane & 3;    // mma fragment coords

    float acc[2][8][4];
#pragma unroll
    for (int mi = 0; mi < 2; ++mi)
#pragma unroll
        for (int ni = 0; ni < 8; ++ni)
#pragma unroll
            for (int r = 0; r < 4; ++r) acc[mi][ni][r] = 0.f;

    for (int kb = 0; kb < K; kb += 16) {
        // Load A tile 128x16 -> As[k][m] with tf32 rounding
#pragma unroll
        for (int u = 0; u < 2; ++u) {
            int id = tid + u * 256;            // 0..511 float4 ids
            int r  = id >> 2;                  // 0..127 (m)
            int c4 = (id & 3) * 4;             // 0,4,8,12 (k)
            float4 av = *(const float4*)&A[(size_t)(by * 128 + r) * K + kb + c4];
            As[(c4 + 0) * GS + r] = to_tf32(av.x);
            As[(c4 + 1) * GS + r] = to_tf32(av.y);
            As[(c4 + 2) * GS + r] = to_tf32(av.z);
            As[(c4 + 3) * GS + r] = to_tf32(av.w);
        }
        // Load B tile 16x128 -> Bs[k][n] with tf32 rounding
#pragma unroll
        for (int u = 0; u < 2; ++u) {
            int id = tid + u * 256;
            int r  = id >> 5;                  // 0..15 (k)
            int c4 = (id & 31) * 4;            // 0..124 (n)
            float4 bv = *(const float4*)&Bm[(size_t)(kb + r) * N + bx * 128 + c4];
            uint4 bu;
            bu.x = to_tf32(bv.x); bu.y = to_tf32(bv.y);
            bu.z = to_tf32(bv.z); bu.w = to_tf32(bv.w);
            *(uint4*)&Bs[r * GS + c4] = bu;
        }
        __syncthreads();

#pragma unroll
        for (int ks = 0; ks < 2; ++ks) {
            const int kk = ks * 8;
            uint32_t a[2][4];
#pragma unroll
            for (int mi = 0; mi < 2; ++mi) {
                int rb = wm * 32 + mi * 16 + gid;
                a[mi][0] = As[(kk + tig)     * GS + rb];
                a[mi][1] = As[(kk + tig)     * GS + rb + 8];
                a[mi][2] = As[(kk + tig + 4) * GS + rb];
                a[mi][3] = As[(kk + tig + 4) * GS + rb + 8];
            }
#pragma unroll
            for (int ni = 0; ni < 8; ++ni) {
                int cb = wn * 64 + ni * 8 + gid;
                uint32_t b0 = Bs[(kk + tig)     * GS + cb];
                uint32_t b1 = Bs[(kk + tig + 4) * GS + cb];
#pragma unroll
                for (int mi = 0; mi < 2; ++mi)
                    mma_tf32(acc[mi][ni], a[mi][0], a[mi][1], a[mi][2], a[mi][3], b0, b1);
            }
        }
        __syncthreads();
    }

    // Epilogue: c0,c1 at (row, col..col+1); c2,c3 at (row+8, ...)
#pragma unroll
    for (int mi = 0; mi < 2; ++mi) {
#pragma unroll
        for (int ni = 0; ni < 8; ++ni) {
            int row = by * 128 + wm * 32 + mi * 16 + gid;
            int col = bx * 128 + wn * 64 + ni * 8 + tig * 2;
            float2 v0 = make_float2(acc[mi][ni][0], acc[mi][ni][1]);
            float2 v1 = make_float2(acc[mi][ni][2], acc[mi][ni][3]);
            *(float2*)&C[(size_t)row * N + col]       = v0;
            *(float2*)&C[(size_t)(row + 8) * N + col] = v1;
        }
    }
}

// ---------------------------------------------------------------------------
// RoPE + split + transpose to head-major [B,N,T,H].
// Rope applied to K and V (NOT Q) per the reference module.
// ---------------------------------------------------------------------------
__global__ void rope_split_kernel(
    const float* __restrict__ qkv,
    const float* __restrict__ cosT, const float* __restrict__ sinT,
    float* __restrict__ q, float* __restrict__ k, float* __restrict__ v)
{
    int idx = blockIdx.x * blockDim.x + threadIdx.x;
    if (idx >= B_ * T_ * NH * FF) return;
    int f = idx & (FF - 1);
    int n = (idx >> 6) & (NH - 1);
    int t = (idx >> 10) & (T_ - 1);
    int b = idx >> 21;

    size_t base = (size_t)(b * T_ + t) * (3 * D_);
    int col = n * HD + 2 * f;
    float c = cosT[t * FF + f];
    float s = sinT[t * FF + f];
    size_t ho = ((size_t)(b * NH + n) * T_ + t) * HD + 2 * f;

    float2 qp = *(const float2*)&qkv[base + col];
    float2 kp = *(const float2*)&qkv[base + D_ + col];
    float2 vp = *(const float2*)&qkv[base + 2 * D_ + col];

    float2 ko = make_float2(kp.x * c - kp.y * s, kp.x * s + kp.y * c);
    float2 vo = make_float2(vp.x * c - vp.y * s, vp.x * s + vp.y * c);

    *(float2*)&q[ho] = qp;
    *(float2*)&k[ho] = ko;
    *(float2*)&v[ho] = vo;
}

// ---------------------------------------------------------------------------
// Flash attention (fp32, causal). One block per (q-tile of 64, head, batch).
// ---------------------------------------------------------------------------
#define QS_STRIDE 132
#define SS_STRIDE 65
#define ATT_SMEM_FLOATS (3 * 64 * QS_STRIDE + 64 * SS_STRIDE + 3 * 64)
#define ATT_SMEM_BYTES  (ATT_SMEM_FLOATS * 4)

__global__ void __launch_bounds__(256) attn_kernel(
    const float* __restrict__ Q, const float* __restrict__ K,
    const float* __restrict__ V, float* __restrict__ O)
{
    const int qt = blockIdx.x, n = blockIdx.y, b = blockIdx.z;
    const int q0 = qt * 64;
    const int tid = threadIdx.x;

    extern __shared__ float sm[];
    float* Qs  = sm;                          // 64 x 132
    float* Ks  = Qs + 64 * QS_STRIDE;         // 64 x 132
    float* Vs  = Ks + 64 * QS_STRIDE;         // 64 x 132
    float* Ss  = Vs + 64 * QS_STRIDE;         // 64 x 65
    float* m_s = Ss + 64 * SS_STRIDE;         // 64
    float* l_s = m_s + 64;                    // 64
    float* a_s = l_s + 64;                    // 64

    const size_t headBase = (size_t)(b * NH + n) * T_ * HD;

#pragma unroll
    for (int t = 0; t < 8; ++t) {
        int idx = tid + t * 256;
        int r = idx >> 5, c4 = (idx & 31) * 4;
        *(float4*)&Qs[r * QS_STRIDE + c4] =
            *(const float4*)&Q[headBase + (size_t)(q0 + r) * HD + c4];
    }
    if (tid < 64) { m_s[tid] = -1e30f; l_s[tid] = 0.f; }

    float o[4][8];
#pragma unroll
    for (int i = 0; i < 4; ++i)
#pragma unroll
        for (int j = 0; j < 8; ++j) o[i][j] = 0.f;

    const int rg = tid >> 4;
    const int cg = tid & 15;
    const float scale = 0.08838834764831845f;  // 1/sqrt(128)

    const int nkt = qt + 1;
    for (int kt = 0; kt < nkt; ++kt) {
        const int k0 = kt * 64;
        __syncthreads();

#pragma unroll
        for (int t = 0; t < 8; ++t) {
            int idx = tid + t * 256;
            int r = idx >> 5, c4 = (idx & 31) * 4;
            size_t g = headBase + (size_t)(k0 + r) * HD + c4;
            *(float4*)&Ks[r * QS_STRIDE + c4] = *(const float4*)&K[g];
            *(float4*)&Vs[r * QS_STRIDE + c4] = *(const float4*)&V[g];
        }
        __syncthreads();

        float acc[4][4];
#pragma unroll
        for (int i = 0; i < 4; ++i)
#pragma unroll
            for (int j = 0; j < 4; ++j) acc[i][j] = 0.f;

#pragma unroll 4
        for (int h4 = 0; h4 < 32; ++h4) {
            float4 qv[4], kv[4];
#pragma unroll
            for (int i = 0; i < 4; ++i)
                qv[i] = *(float4*)&Qs[(rg * 4 + i) * QS_STRIDE + h4 * 4];
#pragma unroll
            for (int j = 0; j < 4; ++j)
                kv[j] = *(float4*)&Ks[(cg * 4 + j) * QS_STRIDE + h4 * 4];
#pragma unroll
            for (int i = 0; i < 4; ++i)
#pragma unroll
                for (int j = 0; j < 4; ++j)
                    acc[i][j] += qv[i].x * kv[j].x + qv[i].y * kv[j].y
                               + qv[i].z * kv[j].z + qv[i].w * kv[j].w;
        }

#pragma unroll
        for (int i = 0; i < 4; ++i) {
            int qg = q0 + rg * 4 + i;
#pragma unroll
            for (int j = 0; j < 4; ++j) {
                int kg = k0 + cg * 4 + j;
                float vsl = acc[i][j] * scale;
                if (kg > qg) vsl = -1e30f;
                Ss[(rg * 4 + i) * SS_STRIDE + cg * 4 + j] = vsl;
            }
        }
        __syncthreads();

        if (tid < 64) {
            float mold = m_s[tid], lold = l_s[tid];
            float* row = &Ss[tid * SS_STRIDE];
            float rmax = -1e30f;
#pragma unroll 8
            for (int c = 0; c < 64; ++c) rmax = fmaxf(rmax, row[c]);
            float mnew = fmaxf(mold, rmax);
            float alpha = __expf(mold - mnew);
            float ssum = 0.f;
#pragma unroll 8
            for (int c = 0; c < 64; ++c) {
                float p = __expf(row[c] - mnew);
                row[c] = p;
                ssum += p;
            }
            m_s[tid] = mnew;
            l_s[tid] = lold * alpha + ssum;
            a_s[tid] = alpha;
        }
        __syncthreads();

        float al[4];
#pragma unroll
        for (int i = 0; i < 4; ++i) al[i] = a_s[rg * 4 + i];
#pragma unroll
        for (int i = 0; i < 4; ++i)
#pragma unroll
            for (int j = 0; j < 8; ++j) o[i][j] *= al[i];

#pragma unroll 4
        for (int kk = 0; kk < 64; ++kk) {
            float p[4];
#pragma unroll
            for (int i = 0; i < 4; ++i) p[i] = Ss[(rg * 4 + i) * SS_STRIDE + kk];
            float4 v0 = *(float4*)&Vs[kk * QS_STRIDE + cg * 8];
            float4 v1 = *(float4*)&Vs[kk * QS_STRIDE + cg * 8 + 4];
#pragma unroll
            for (int i = 0; i < 4; ++i) {
                o[i][0] += p[i] * v0.x; o[i][1] += p[i] * v0.y;
                o[i][2] += p[i] * v0.z; o[i][3] += p[i] * v0.w;
                o[i][4] += p[i] * v1.x; o[i][5] += p[i] * v1.y;
                o[i][6] += p[i] * v1.z; o[i][7] += p[i] * v1.w;
            }
        }
    }

#pragma unroll
    for (int i = 0; i < 4; ++i) {
        int qg = q0 + rg * 4 + i;
        float inv = 1.f / l_s[rg * 4 + i];
        float4 w0, w1;
        w0.x = o[i][0] * inv; w0.y = o[i][1] * inv;
        w0.z = o[i][2] * inv; w0.w = o[i][3] * inv;
        w1.x = o[i][4] * inv; w1.y = o[i][5] * inv;
        w1.z = o[i][6] * inv; w1.w = o[i][7] * inv;
        size_t ob = (size_t)(b * T_ + qg) * D_ + n * HD + cg * 8;
        *(float4*)&O[ob]     = w0;
        *(float4*)&O[ob + 4] = w1;
    }
}

// ---------------------------------------------------------------------------
// Launch
// ---------------------------------------------------------------------------
extern "C" void kernel_launch(void* const* d_in, const int* in_sizes, int n_in,
                              void* d_out, int out_size)
{
    const float* x      = (const float*)d_in[0];
    // d_in[1] = mask (causal, structurally known) -- unused
    const float* cosT   = (const float*)d_in[2];
    const float* sinT   = (const float*)d_in[3];
    const float* w_attn = (const float*)d_in[4];
    const float* w_out  = (const float*)d_in[5];
    float* out = (float*)d_out;

    float *qkv, *q, *k, *v, *ao;
    cudaGetSymbolAddress((void**)&qkv, g_qkv);
    cudaGetSymbolAddress((void**)&q,   g_q);
    cudaGetSymbolAddress((void**)&k,   g_k);
    cudaGetSymbolAddress((void**)&v,   g_v);
    cudaGetSymbolAddress((void**)&ao,  g_ao);

    // 1) QKV projection: [4096,2048] @ [2048,6144]  (tf32 tensor cores)
    tf32_gemm_kernel<<<dim3(3 * D_ / 128, M_ / 128), 256>>>(x, w_attn, qkv, M_, 3 * D_, D_);

    // 2) RoPE (K,V) + split + transpose to head-major
    {
        int total = B_ * T_ * NH * FF;
        rope_split_kernel<<<(total + 255) / 256, 256>>>(qkv, cosT, sinT, q, k, v);
    }

    // 3) Causal flash attention
    cudaFuncSetAttribute(attn_kernel, cudaFuncAttributeMaxDynamicSharedMemorySize,
                         ATT_SMEM_BYTES);
    attn_kernel<<<dim3(T_ / 64, NH, B_), 256, ATT_SMEM_BYTES>>>(q, k, v, ao);

    // 4) Output projection: [4096,2048] @ [2048,2048]  (tf32 tensor cores)
    tf32_gemm_kernel<<<dim3(D_ / 128, M_ / 128), 256>>>(ao, w_out, out, M_, D_, D_);
}